// round 8
// baseline (speedup 1.0000x reference)
#include <cuda_runtime.h>
#include <cstdint>

// Problem constants
#define B_  128
#define C1_ 128
#define C2_ 14
#define S_  14
#define H_  256

#define THREADS 224   // 7 warps

// A (x window) smem geometry, in 8-byte PAIRS:
//   pair-addr = PM*mp + PN*n + (4*step + t);  PM=280 (=8 mod 16), PN=20 (=4 mod 16)
//   -> LDS.64 bank pattern 4q+t (conflict-free), rows 16B-aligned for cp.async
#define PM 280
#define PN 20
#define XBUF_W (16 * PM * 2)          // 8960 words per buffer
#define BS_W   (2 * XBUF_W)           // 17920
#define BS_BUF 1024                   // words per B chunk
#define CS_STRIDE 36
#define SMEM_WORDS (BS_W + 3 * BS_BUF)   // 20992 words = 83968 B

// GEMM-ready gmem scratch (written by prep kernels each launch)
__device__ float g_xpre[(size_t)B_ * 16 * 14 * 4 * 32];   // 14.7 MB
__device__ float g_wpre[12 * 8 * 1024];                   // 393 KB

__device__ __forceinline__ float tf32r(float v) {
    float r;
    asm("cvt.rna.tf32.f32 %0, %1;" : "=f"(r) : "f"(v));
    return r;
}

__device__ __forceinline__ void mma_tf32(float c[4],
                                         unsigned a0, unsigned a1, unsigned a2, unsigned a3,
                                         unsigned b0, unsigned b1) {
    asm volatile(
        "mma.sync.aligned.m16n8k8.row.col.f32.tf32.tf32.f32 "
        "{%0,%1,%2,%3}, {%4,%5,%6,%7}, {%8,%9}, {%0,%1,%2,%3};"
        : "+f"(c[0]), "+f"(c[1]), "+f"(c[2]), "+f"(c[3])
        : "r"(a0), "r"(a1), "r"(a2), "r"(a3), "r"(b0), "r"(b1));
}

__device__ __forceinline__ void cp16(unsigned dst, const void* src) {
    asm volatile("cp.async.cg.shared.global [%0], [%1], 16;"
                 :: "r"(dst), "l"(src) : "memory");
}
#define CP_COMMIT() asm volatile("cp.async.commit_group;" ::: "memory")
#define CP_WAIT1()  asm volatile("cp.async.wait_group 1;" ::: "memory")

// ---------------------------------------------------------------------------
// prep_x: build xpre[b][mp:16][n:14][jb:4][pp:32], tf32-rounded, zero pads.
// pp = 2*p + h; p = 4*step + t; element = xpad[b, jb*32 + 8*step+t+4*h, n, mp]
// Block = (b*4 + jb): reads its 6272-float x slice coalesced, writes 128B rows.
// ---------------------------------------------------------------------------
__global__ __launch_bounds__(256) void prep_x(const float* __restrict__ x) {
    __shared__ float xs[32 * 196];
    const int blk = blockIdx.x;
    const int b   = blk >> 2;
    const int jb  = blk & 3;

    const float* src = x + (size_t)b * 25088 + jb * 6272;
    for (int k = threadIdx.x; k < 6272; k += 256) xs[k] = src[k];
    __syncthreads();

    float* dst = g_xpre + ((size_t)b * 16 * 14 * 4 + jb) * 32;
    for (int widx = threadIdx.x; widx < 16 * 14 * 32; widx += 256) {
        int pp = widx & 31;
        int nn = (widx >> 5) % 14;
        int mp = (widx >> 5) / 14;
        float v = 0.0f;
        if (mp >= 1 && mp <= 14) {
            int p = pp >> 1, h = pp & 1;
            int j = 8 * (p >> 2) + (p & 3) + 4 * h;
            v = tf32r(xs[j * 196 + nn * 14 + (mp - 1)]);
        }
        dst[(size_t)(mp * 14 + nn) * (4 * 32) + pp] = v;
    }
}

// ---------------------------------------------------------------------------
// prep_w: build wpre[c:12][hh:8][step:4][hl:32][t:4][h2:2], tf32-rounded.
// value = w1[j = (c/3)*32 + 8*step + t + 4*h2,  i = c%3,  hcol = hh*32+hl]
// ---------------------------------------------------------------------------
__global__ __launch_bounds__(256) void prep_w(const float* __restrict__ w1) {
    int idx = blockIdx.x * 256 + threadIdx.x;
    if (idx >= 12 * 8 * 1024) return;
    int h2   = idx & 1;
    int t    = (idx >> 1) & 3;
    int hl   = (idx >> 3) & 31;
    int step = (idx >> 8) & 3;
    int hh   = (idx >> 10) & 7;
    int c    = idx >> 13;
    int j    = (c / 3) * 32 + 8 * step + t + 4 * h2;
    int i    = c % 3;
    int hcol = hh * 32 + hl;
    g_wpre[idx] = tf32r(w1[(size_t)(j * 3 + i) * H_ + hcol]);
}

// ---------------------------------------------------------------------------
// Fused GEMM + roll epilogue. Block = (b, 32-h chunk). M=224 rows r=(m*14+n),
// N=32, K=384=(i,j), tf32 MMA. cp.async pipelined staging (3-deep B, 2-deep x,
// prefetch distance 2 chunks). A and B both k-paired -> all-LDS.64 feed.
// ---------------------------------------------------------------------------
__global__ void __launch_bounds__(THREADS, 2) fused_kernel(
    const float* __restrict__ w0,      // (H, 2)
    const int*   __restrict__ shift_p, // scalar (may be null -> 1)
    float*       __restrict__ out)     // (B, H, C2, S)
{
    extern __shared__ float sm[];
    const unsigned sbase = (unsigned)__cvta_generic_to_shared(sm);

    const int bid = blockIdx.x;
    const int b   = bid >> 3;
    const int hh  = bid & 7;
    const int h0  = hh * 32;

    const int tid  = threadIdx.x;
    const int w    = tid >> 5;
    const int lane = tid & 31;
    const int t    = lane & 3;
    const int q    = lane >> 2;

    // staging thread mapping (x): one 32-float row per thread
    const int smp = tid / 14;
    const int snn = tid - smp * 14;
    const float* xsrc0 = g_xpre + (((size_t)b * 16 + smp) * 14 + snn) * (4 * 32);
    const unsigned xdst0 = sbase + (unsigned)((PM * smp + PN * snn) * 2) * 4u;

    auto issue_x = [&](int jb) {
        const float* src = xsrc0 + jb * 32;
        unsigned dst = xdst0 + (unsigned)((jb & 1) * XBUF_W) * 4u;
#pragma unroll
        for (int k = 0; k < 8; ++k) cp16(dst + 16u * k, src + 4 * k);
    };
    auto issue_b = [&](int c2, int buf) {
        const float* src = g_wpre + ((size_t)c2 * 8 + hh) * 1024;
        unsigned dst = sbase + (unsigned)(BS_W + buf * BS_BUF) * 4u;
        cp16(dst + 16u * tid, src + 4 * tid);
        if (tid < 32) cp16(dst + 16u * (tid + 224), src + 4 * (tid + 224));
    };

    // Per-thread A base offsets (words): pa[u] = 2*(PM*mr + PN*nr + t)
    int pa[4];
#pragma unroll
    for (int u = 0; u < 4; ++u) {
        int r  = 32 * w + q + 8 * u;
        int mr = r / 14;
        int nr = r - mr * 14;
        if (mr > 13) mr = 13;          // pad rows -> harmless valid data
        pa[u] = 2 * (PM * mr + PN * nr + t);
    }

    // ---- Prologue: prefetch chunk 0 (x0+B0) and chunk 1 (B1) ----
    issue_x(0);
    issue_b(0, 0);
    CP_COMMIT();
    issue_b(1, 1);
    CP_COMMIT();

    float cf[8][4];
#pragma unroll
    for (int f = 0; f < 8; ++f)
#pragma unroll
        for (int r = 0; r < 4; ++r) cf[f][r] = 0.0f;

    const int pbq = q * 8 + 2 * t;

    // ---- Main loop: 12 chunks = 4 j-blocks x 3 i ----
#pragma unroll 1
    for (int jb = 0; jb < 4; ++jb) {
        const int xw = (jb & 1) * XBUF_W;

#pragma unroll
        for (int ii = 0; ii < 3; ++ii) {
            CP_WAIT1();
            __syncthreads();

            // prefetch chunk c+2 (after barrier: target buffers are free)
            if (3 * jb + ii < 10) {
                if (ii == 1) issue_x(jb + 1);
                issue_b(3 * jb + ii + 2, (ii + 2) % 3);
                CP_COMMIT();
            }

            const int bw = BS_W + ii * BS_BUF + pbq;
            const int aw = xw + 560 * ii;            // 2*PM*ii

#pragma unroll
            for (int step = 0; step < 4; ++step) {
                const int ao = aw + 8 * step;
                float2 aA = *reinterpret_cast<const float2*>(&sm[pa[0] + ao]);
                float2 aB = *reinterpret_cast<const float2*>(&sm[pa[1] + ao]);
                float2 aC = *reinterpret_cast<const float2*>(&sm[pa[2] + ao]);
                float2 aD = *reinterpret_cast<const float2*>(&sm[pa[3] + ao]);
#pragma unroll
                for (int fn = 0; fn < 4; ++fn) {
                    float2 bp = *reinterpret_cast<const float2*>(
                        &sm[bw + step * 256 + fn * 64]);
                    unsigned b0 = __float_as_uint(bp.x);
                    unsigned b1 = __float_as_uint(bp.y);
                    mma_tf32(cf[fn],
                             __float_as_uint(aA.x), __float_as_uint(aB.x),
                             __float_as_uint(aA.y), __float_as_uint(aB.y), b0, b1);
                    mma_tf32(cf[4 + fn],
                             __float_as_uint(aC.x), __float_as_uint(aD.x),
                             __float_as_uint(aC.y), __float_as_uint(aD.y), b0, b1);
                }
            }
        }
    }

    // ---- Write C tile to smem rows [r][36] (aliases x buffer 0; chunk 11
    //      reads only x buffer 1 + B region, so no extra barrier needed) ----
#pragma unroll
    for (int fm = 0; fm < 2; ++fm) {
#pragma unroll
        for (int fn = 0; fn < 4; ++fn) {
            const float* cc = cf[fm * 4 + fn];
            int r1  = 32 * w + 16 * fm + q;
            int r2  = r1 + 8;
            int col = 8 * fn + 2 * t;
            *reinterpret_cast<float2*>(&sm[r1 * CS_STRIDE + col]) = make_float2(cc[0], cc[1]);
            *reinterpret_cast<float2*>(&sm[r2 * CS_STRIDE + col]) = make_float2(cc[2], cc[3]);
        }
    }
    __syncthreads();

    // ---- Fused roll epilogue ----
    const int s   = shift_p ? shift_p[0] : 1;
    const int s28 = ((s % 28) + 28) % 28;
    const int s14 = ((s % 14) + 14) % 14;

#pragma unroll
    for (int it = 0; it < 2; ++it) {
        int idx = it * THREADS + tid;   // 0..447
        int h_l = idx & 31;
        int nb  = idx >> 5;             // 0..13

        float2 w0p = __ldg(reinterpret_cast<const float2*>(w0) + (h0 + h_l));

        int n2[2];
        float wv[2];
#pragma unroll
        for (int e = 0; e < 2; ++e) {
            int g  = (nb * 2 + e - s28 + 56) % 28;
            int n1 = g >> 1;
            int e1 = g & 1;
            n2[e]  = (n1 - s14 + 14) % 14;
            wv[e]  = e1 ? w0p.y : w0p.x;
        }

        float* orow = out + (size_t)(b * H_ + h0 + h_l) * (C2_ * S_) + nb * S_;
#pragma unroll
        for (int mm = 0; mm < 7; ++mm) {
            int m0 = 2 * mm, m1 = 2 * mm + 1;
            float v0 = sm[(m0 * 14 + n2[0]) * CS_STRIDE + h_l] * wv[0]
                     + sm[(m0 * 14 + n2[1]) * CS_STRIDE + h_l] * wv[1];
            float v1 = sm[(m1 * 14 + n2[0]) * CS_STRIDE + h_l] * wv[0]
                     + sm[(m1 * 14 + n2[1]) * CS_STRIDE + h_l] * wv[1];
            *reinterpret_cast<float2*>(orow + m0) = make_float2(v0, v1);
        }
    }
}

// ---------------------------------------------------------------------------
extern "C" void kernel_launch(void* const* d_in, const int* in_sizes, int n_in,
                              void* d_out, int out_size)
{
    const float* x     = (const float*)d_in[0];
    const float* w0    = (const float*)d_in[1];
    const float* w1    = (const float*)d_in[2];
    const int*   shift = (n_in >= 4) ? (const int*)d_in[3] : nullptr;

    (void)in_sizes; (void)out_size;

    prep_x<<<B_ * 4, 256>>>(x);
    prep_w<<<(12 * 8 * 1024 + 255) / 256, 256>>>(w1);

    cudaFuncSetAttribute(fused_kernel,
                         cudaFuncAttributeMaxDynamicSharedMemorySize,
                         SMEM_WORDS * 4);
    fused_kernel<<<B_ * 8, THREADS, SMEM_WORDS * 4>>>(w0, shift, (float*)d_out);
}